// round 3
// baseline (speedup 1.0000x reference)
#include <cuda_runtime.h>

// LabelLoss: out[b] = sum_{n,c<7} (pred[b,n,c] - gt[b,n,c])^2
// pred, gt: [256, 16384, 8] fp32. Pure HBM-bound streaming reduction.
//
// R3: fine-grained chunks + multi-wave (HW work-stealing on wave>=2) to remove
// the single-wave slowest-SM tail. Each block = one fully-unrolled pass of
// 256 threads x 4 float4 per stream (32 KB total), fully coalesced.

#define B_DIM       256
#define N_OBJ       16384
#define THREADS     256
#define SPLIT       32                        // chunks per batch row -> grid 8192
#define F4_PER_ROW  (N_OBJ * 2)               // 32768 float4 per batch row
#define F4_PER_BLK  (F4_PER_ROW / SPLIT)      // 1024 float4 per block (per stream)
#define UNROLL      4                         // THREADS*UNROLL == F4_PER_BLK

__global__ void zero_out_kernel(float* __restrict__ out) {
    int i = threadIdx.x;
    if (i < B_DIM) out[i] = 0.0f;
}

__global__ __launch_bounds__(THREADS, 8)
void label_loss_kernel(const float* __restrict__ pred,
                       const float* __restrict__ gt,
                       float* __restrict__ out) {
    const int b = blockIdx.x;
    const int s = blockIdx.y;

    const float4* __restrict__ p =
        reinterpret_cast<const float4*>(pred) + (size_t)b * F4_PER_ROW + s * F4_PER_BLK;
    const float4* __restrict__ g =
        reinterpret_cast<const float4*>(gt)   + (size_t)b * F4_PER_ROW + s * F4_PER_BLK;

    // float4-index parity for this thread is constant (strides even):
    // odd float4 -> its .w is channel 7 (excluded from loss).
    const float wsel = (threadIdx.x & 1) ? 0.0f : 1.0f;

    // One fully-unrolled pass: 4 p + 4 g = 8 front-batched LDG.128 per thread.
    float4 pv[UNROLL], gv[UNROLL];
    #pragma unroll
    for (int u = 0; u < UNROLL; u++) {
        const int idx = u * THREADS + threadIdx.x;
        pv[u] = p[idx];
        gv[u] = g[idx];
    }

    float acc = 0.0f;
    #pragma unroll
    for (int u = 0; u < UNROLL; u++) {
        float d0 = pv[u].x - gv[u].x;
        float d1 = pv[u].y - gv[u].y;
        float d2 = pv[u].z - gv[u].z;
        float d3 = (pv[u].w - gv[u].w) * wsel;   // channel 7 masked on odd lanes
        acc += d0*d0 + d1*d1 + d2*d2 + d3*d3;
    }

    // Warp reduction
    #pragma unroll
    for (int off = 16; off > 0; off >>= 1)
        acc += __shfl_xor_sync(0xFFFFFFFFu, acc, off);

    // Cross-warp reduction via shared memory
    __shared__ float warp_sums[THREADS / 32];
    const int lane = threadIdx.x & 31;
    const int wid  = threadIdx.x >> 5;
    if (lane == 0) warp_sums[wid] = acc;
    __syncthreads();

    if (wid == 0) {
        float v = (lane < THREADS / 32) ? warp_sums[lane] : 0.0f;
        #pragma unroll
        for (int off = 4; off > 0; off >>= 1)
            v += __shfl_xor_sync(0xFFFFFFFFu, v, off);
        if (lane == 0)
            atomicAdd(out + b, v);
    }
}

extern "C" void kernel_launch(void* const* d_in, const int* in_sizes, int n_in,
                              void* d_out, int out_size) {
    const float* pred = (const float*)d_in[0];
    const float* gt   = (const float*)d_in[1];
    float* out        = (float*)d_out;

    zero_out_kernel<<<1, B_DIM>>>(out);

    dim3 grid(B_DIM, SPLIT);
    label_loss_kernel<<<grid, THREADS>>>(pred, gt, out);
}